// round 1
// baseline (speedup 1.0000x reference)
#include <cuda_runtime.h>
#include <cstdint>

// x: [B=16, C=8, T=262144] fp32, row-major.
// out = x * (c == 0 ? 1.0f : 0.5f)
// T = 2^18, C = 2^3 -> channel = (flat_idx >> 18) & 7.

static constexpr int B = 16;
static constexpr int C = 8;
static constexpr long long T = 262144;          // 2^18
static constexpr long long N_ELEMS = (long long)B * C * T;   // 33,554,432
static constexpr long long N_VEC4 = N_ELEMS / 4;             // 8,388,608

__global__ void __launch_bounds__(256) channel_scale_kernel(
    const float4* __restrict__ x, float4* __restrict__ out)
{
    long long i = (long long)blockIdx.x * blockDim.x + threadIdx.x;
    // flat element index of this vector's first lane
    long long e = i << 2;
    // channel = (e / T) % C ; T=2^18, C=8 -> shifts
    int c = (int)((e >> 18) & 7);
    float s = (c == 0) ? 1.0f : 0.5f;

    float4 v = x[i];
    v.x *= s; v.y *= s; v.z *= s; v.w *= s;
    out[i] = v;
}

extern "C" void kernel_launch(void* const* d_in, const int* in_sizes, int n_in,
                              void* d_out, int out_size)
{
    const float4* x = (const float4*)d_in[0];
    float4* out = (float4*)d_out;

    const int threads = 256;
    const int blocks = (int)(N_VEC4 / threads);   // 32768, exact
    channel_scale_kernel<<<blocks, threads>>>(x, out);
}

// round 2
// speedup vs baseline: 1.0088x; 1.0088x over previous
#include <cuda_runtime.h>
#include <cstdint>

// x: [B=16, C=8, T=262144] fp32 row-major.
// out = x * (c == 0 ? 1.0f : 0.5f)
// Per-float4 flat index i: element index e = 4*i, channel = (e / 2^18) & 7 = (i >> 16) & 7.

static constexpr long long N_ELEMS = 16LL * 8LL * 262144LL;   // 33,554,432
static constexpr long long N_VEC4  = N_ELEMS / 4;             // 8,388,608
static constexpr int       UNROLL  = 4;
static constexpr long long STRIDE  = N_VEC4 / UNROLL;         // 2,097,152 float4s
static constexpr int       THREADS = 256;
static constexpr int       BLOCKS  = (int)(STRIDE / THREADS); // 8192, exact

__global__ void __launch_bounds__(THREADS) channel_scale_kernel(
    const float4* __restrict__ x, float4* __restrict__ out)
{
    const long long i0 = (long long)blockIdx.x * THREADS + threadIdx.x;

    // Front-batch 4 independent 128-bit loads (MLP=4 per thread).
    float4 v[UNROLL];
#pragma unroll
    for (int k = 0; k < UNROLL; k++) {
        v[k] = __ldcs(&x[i0 + (long long)k * STRIDE]);
    }

#pragma unroll
    for (int k = 0; k < UNROLL; k++) {
        const long long i = i0 + (long long)k * STRIDE;
        // channel 0 iff bits [16:19) of the float4 index are zero
        const float s = ((i & (7LL << 16)) == 0) ? 1.0f : 0.5f;
        float4 w = v[k];
        w.x *= s; w.y *= s; w.z *= s; w.w *= s;
        __stcs(&out[i], w);
    }
}

extern "C" void kernel_launch(void* const* d_in, const int* in_sizes, int n_in,
                              void* d_out, int out_size)
{
    const float4* x = (const float4*)d_in[0];
    float4* out = (float4*)d_out;
    channel_scale_kernel<<<BLOCKS, THREADS>>>(x, out);
}